// round 1
// baseline (speedup 1.0000x reference)
#include <cuda_runtime.h>
#include <math.h>

// Problem dims (fixed by the dataset)
#define B_    2
#define L_    1024
#define DM    1024
#define DI    2048
#define NS    16
#define DTR   64
#define DC    4
#define NTOK  (B_ * L_)      // 2048 tokens
#define XDBLW 96             // DT_RANK + 2*N

// ---------------------------------------------------------------------------
// Scratch (static __device__ arrays -- allocation-free per harness rules)
// ---------------------------------------------------------------------------
__device__ float g_xz   [(size_t)NTOK * 2 * DI];  // (B,L,2*DI)  33.5 MB
__device__ float g_xconv[(size_t)NTOK * DI];      // conv+silu   16.8 MB
__device__ float g_xdbl [(size_t)NTOK * XDBLW];   // dt|B|C       0.8 MB
__device__ float g_delta[(size_t)NTOK * DI];      // softplus    16.8 MB
__device__ float g_ybuf [(size_t)NTOK * DI];      // scan out    16.8 MB

// ---------------------------------------------------------------------------
// Helpers
// ---------------------------------------------------------------------------
__device__ __forceinline__ float silu_f(float x) {
    return x / (1.0f + __expf(-x));
}
__device__ __forceinline__ float softplus_f(float x) {
    return (x > 20.0f) ? x : log1pf(__expf(x));
}

// ---------------------------------------------------------------------------
// Generic 128x128x8 fp32 SGEMM (row-major A[M,K], B[K,N] -> C[M,N])
// EPI: 0 = plain store, 1 = softplus(acc + bias[col])
// All M,N multiples of 128; K multiple of 8; lda/ldb rows 16B-aligned.
// ---------------------------------------------------------------------------
template <int EPI>
__global__ void __launch_bounds__(256)
sgemm128(const float* __restrict__ A, const float* __restrict__ Bm,
         float* __restrict__ C, int M, int N, int K,
         int lda, int ldb, int ldc, const float* __restrict__ bias)
{
    __shared__ float As[8][128];
    __shared__ float Bs[8][128];

    const int tid = threadIdx.x;
    const int bm  = blockIdx.y * 128;
    const int bn  = blockIdx.x * 128;

    const int arow = tid >> 1;          // 0..127
    const int acol = (tid & 1) * 4;     // 0 or 4
    const int brow = tid >> 5;          // 0..7
    const int bcol = (tid & 31) * 4;    // 0..124

    const float* Aptr = A + (size_t)(bm + arow) * lda + acol;
    const float* Bptr = Bm + (size_t)brow * ldb + bn + bcol;

    const int ty = tid >> 4;            // 0..15 -> row group
    const int tx = tid & 15;            // 0..15 -> col group

    float acc[8][8];
    #pragma unroll
    for (int i = 0; i < 8; i++)
        #pragma unroll
        for (int j = 0; j < 8; j++) acc[i][j] = 0.0f;

    for (int kk = 0; kk < K; kk += 8) {
        float4 av = *(const float4*)(Aptr + kk);
        As[acol + 0][arow] = av.x;
        As[acol + 1][arow] = av.y;
        As[acol + 2][arow] = av.z;
        As[acol + 3][arow] = av.w;
        *(float4*)&Bs[brow][bcol] = *(const float4*)(Bptr + (size_t)kk * ldb);
        __syncthreads();

        #pragma unroll
        for (int k = 0; k < 8; ++k) {
            float a[8], b[8];
            *(float4*)(a)     = *(const float4*)&As[k][ty * 8];
            *(float4*)(a + 4) = *(const float4*)&As[k][ty * 8 + 4];
            *(float4*)(b)     = *(const float4*)&Bs[k][tx * 8];
            *(float4*)(b + 4) = *(const float4*)&Bs[k][tx * 8 + 4];
            #pragma unroll
            for (int i = 0; i < 8; i++)
                #pragma unroll
                for (int j = 0; j < 8; j++)
                    acc[i][j] = fmaf(a[i], b[j], acc[i][j]);
        }
        __syncthreads();
    }

    #pragma unroll
    for (int i = 0; i < 8; i++) {
        int row = bm + ty * 8 + i;
        int col = bn + tx * 8;
        float out[8];
        #pragma unroll
        for (int j = 0; j < 8; j++) {
            float v = acc[i][j];
            if (EPI == 1) v = softplus_f(v + bias[col + j]);
            out[j] = v;
        }
        float* cp = C + (size_t)row * ldc + col;
        *(float4*)(cp)     = *(const float4*)(out);
        *(float4*)(cp + 4) = *(const float4*)(out + 4);
    }
}

// ---------------------------------------------------------------------------
// Causal depthwise conv (k=4) + SiLU on the x half of xz
// ---------------------------------------------------------------------------
__global__ void conv_silu_kernel(const float* __restrict__ xz,
                                 const float* __restrict__ kw,   // (4, DI)
                                 const float* __restrict__ kb,   // (DI,)
                                 float* __restrict__ out)        // (NTOK, DI)
{
    int idx = blockIdx.x * blockDim.x + threadIdx.x;
    if (idx >= NTOK * DI) return;
    int d = idx & (DI - 1);
    int t = idx >> 11;           // token index b*L + l
    int l = t & (L_ - 1);

    float acc = kb[d];
    #pragma unroll
    for (int i = 0; i < DC; i++) {
        int ls = l - (DC - 1) + i;
        if (ls >= 0)
            acc = fmaf(xz[(size_t)(t - (DC - 1) + i) * (2 * DI) + d],
                       kw[i * DI + d], acc);
    }
    out[idx] = silu_f(acc);
}

// ---------------------------------------------------------------------------
// x_dbl = xconv @ Wx   (NTOK x 96, K=2048). One block per token row.
// ---------------------------------------------------------------------------
__global__ void __launch_bounds__(96)
xdbl_kernel(const float* __restrict__ xc, const float* __restrict__ Wx,
            float* __restrict__ out)
{
    __shared__ float sh[DI];
    const int row = blockIdx.x;
    const int col = threadIdx.x;   // 0..95
    const float* a = xc + (size_t)row * DI;
    for (int k = col; k < DI; k += 96) sh[k] = a[k];
    __syncthreads();

    float acc = 0.0f;
    #pragma unroll 8
    for (int k = 0; k < DI; k++)
        acc = fmaf(sh[k], Wx[(size_t)k * XDBLW + col], acc);
    out[(size_t)row * XDBLW + col] = acc;
}

// ---------------------------------------------------------------------------
// Selective scan. One thread per (channel, state-n); 16-lane groups reduce y.
// Output: ybuf = (scan_y + u*Dskip) * silu(z)
// ---------------------------------------------------------------------------
__global__ void __launch_bounds__(256)
scan_kernel(const float* __restrict__ delta, const float* __restrict__ u,
            const float* __restrict__ xdbl,  const float* __restrict__ xz,
            const float* __restrict__ A_log, const float* __restrict__ Dskip,
            float* __restrict__ y)
{
    const int tid = threadIdx.x;
    const int grp = tid >> 4;                 // channel group within block
    const int n   = tid & 15;                 // state index
    const int c   = blockIdx.x * 16 + grp;    // global channel 0..B*DI-1
    const int b   = c >> 11;                  // / DI
    const int d   = c & (DI - 1);

    const float An = -__expf(A_log[d * NS + n]);
    const float Dd = Dskip[d];

    const float* drow = delta + (size_t)b * L_ * DI + d;
    const float* urow = u     + (size_t)b * L_ * DI + d;
    const float* zrow = xz    + (size_t)b * L_ * (2 * DI) + DI + d;
    const float* brow = xdbl  + (size_t)b * L_ * XDBLW + DTR + n;
    float*       yrow = y     + (size_t)b * L_ * DI + d;

    float x = 0.0f;
    for (int l = 0; l < L_; ++l) {
        float dv = drow[(size_t)l * DI];
        float uv = urow[(size_t)l * DI];
        float Bn = brow[(size_t)l * XDBLW];
        float Cn = brow[(size_t)l * XDBLW + NS];

        float dA = __expf(dv * An);
        x = fmaf(dA, x, dv * Bn * uv);

        float v = x * Cn;
        v += __shfl_xor_sync(0xffffffffu, v, 1, 16);
        v += __shfl_xor_sync(0xffffffffu, v, 2, 16);
        v += __shfl_xor_sync(0xffffffffu, v, 4, 16);
        v += __shfl_xor_sync(0xffffffffu, v, 8, 16);

        if (n == 0) {
            float zv = zrow[(size_t)l * (2 * DI)];
            yrow[(size_t)l * DI] = (v + uv * Dd) * silu_f(zv);
        }
    }
}

// ---------------------------------------------------------------------------
// Launch
// ---------------------------------------------------------------------------
extern "C" void kernel_launch(void* const* d_in, const int* in_sizes, int n_in,
                              void* d_out, int out_size)
{
    const float* hs      = (const float*)d_in[0];  // (B,L,DM)
    const float* Win     = (const float*)d_in[1];  // (DM, 2*DI)
    const float* Wx      = (const float*)d_in[2];  // (DI, 96)
    const float* Wdt     = (const float*)d_in[3];  // (DTR, DI)
    const float* dt_bias = (const float*)d_in[4];  // (DI,)
    const float* Wout    = (const float*)d_in[5];  // (DI, DM)
    const float* dwk     = (const float*)d_in[6];  // (4, DI)
    const float* dwb     = (const float*)d_in[7];  // (DI,)
    const float* A_log   = (const float*)d_in[8];  // (DI, NS)
    const float* Dskip   = (const float*)d_in[9];  // (DI,)
    float* out = (float*)d_out;

    float *xz, *xc, *xd, *dl, *yb;
    cudaGetSymbolAddress((void**)&xz, g_xz);
    cudaGetSymbolAddress((void**)&xc, g_xconv);
    cudaGetSymbolAddress((void**)&xd, g_xdbl);
    cudaGetSymbolAddress((void**)&dl, g_delta);
    cudaGetSymbolAddress((void**)&yb, g_ybuf);

    // 1) xz = hidden @ Win            (2048 x 4096, K=1024)
    sgemm128<0><<<dim3(4096 / 128, 2048 / 128), 256>>>(
        hs, Win, xz, NTOK, 2 * DI, DM, DM, 2 * DI, 2 * DI, nullptr);

    // 2) depthwise causal conv + silu on x half
    conv_silu_kernel<<<(NTOK * DI + 255) / 256, 256>>>(xz, dwk, dwb, xc);

    // 3) x_dbl = xconv @ Wx           (2048 x 96, K=2048)
    xdbl_kernel<<<NTOK, 96>>>(xc, Wx, xd);

    // 4) delta = softplus(dt @ Wdt + dt_bias)   (2048 x 2048, K=64)
    sgemm128<1><<<dim3(2048 / 128, 2048 / 128), 256>>>(
        xd, Wdt, dl, NTOK, DI, DTR, XDBLW, DI, DI, dt_bias);

    // 5) selective scan (+skip, *silu(z))
    scan_kernel<<<(B_ * DI) / 16, 256>>>(dl, xc, xd, xz, A_log, Dskip, yb);

    // 6) out = y @ Wout               (2048 x 1024, K=2048)
    sgemm128<0><<<dim3(1024 / 128, 2048 / 128), 256>>>(
        yb, Wout, out, NTOK, DM, DI, DI, DM, DM, nullptr);
}

// round 2
// speedup vs baseline: 1.5010x; 1.5010x over previous
#include <cuda_runtime.h>
#include <math.h>
#include <stdint.h>

// Problem dims (fixed by the dataset)
#define B_    2
#define L_    1024
#define DM    1024
#define DI    2048
#define NS    16
#define DTR   64
#define DC    4
#define NTOK  (B_ * L_)      // 2048 tokens
#define XDBLW 96             // DT_RANK + 2*N

// ---------------------------------------------------------------------------
// Scratch (static __device__ arrays -- allocation-free per harness rules)
// ---------------------------------------------------------------------------
__device__ float g_xz   [(size_t)NTOK * 2 * DI];  // (B,L,2*DI)
__device__ float g_xconv[(size_t)NTOK * DI];      // conv+silu
__device__ float g_xdbl [(size_t)NTOK * XDBLW];   // dt|B|C
__device__ float g_delta[(size_t)NTOK * DI];      // softplus
__device__ float g_ybuf [(size_t)NTOK * DI];      // scan out

// ---------------------------------------------------------------------------
// Helpers
// ---------------------------------------------------------------------------
__device__ __forceinline__ float silu_f(float x) {
    return x / (1.0f + __expf(-x));
}
__device__ __forceinline__ float softplus_f(float x) {
    return (x > 20.0f) ? x : log1pf(__expf(x));
}
__device__ __forceinline__ uint32_t f2tf32(float f) {
    uint32_t u;
    asm("cvt.rna.tf32.f32 %0, %1;\n" : "=r"(u) : "f"(f));
    return u;
}
__device__ __forceinline__ void mma_tf32(float* c, const uint32_t* a, const uint32_t* b) {
    asm volatile(
        "mma.sync.aligned.m16n8k8.row.col.f32.tf32.tf32.f32 "
        "{%0,%1,%2,%3}, {%4,%5,%6,%7}, {%8,%9}, {%0,%1,%2,%3};\n"
        : "+f"(c[0]), "+f"(c[1]), "+f"(c[2]), "+f"(c[3])
        : "r"(a[0]), "r"(a[1]), "r"(a[2]), "r"(a[3]), "r"(b[0]), "r"(b[1]));
}

#define CPA16(smp, gp) \
    asm volatile("cp.async.cg.shared.global [%0], [%1], 16;\n" :: "r"(smp), "l"(gp))
#define CPA_COMMIT()  asm volatile("cp.async.commit_group;\n")
#define CPA_WAIT1()   asm volatile("cp.async.wait_group 1;\n" ::: "memory")
#define CPA_WAIT0()   asm volatile("cp.async.wait_group 0;\n" ::: "memory")

// ---------------------------------------------------------------------------
// TF32 tensor-core GEMM: C[M,N] = A[M,K] @ B[K,N], all row-major fp32.
// Block tile 128x128, BK=16, 256 threads (8 warps; warp tile 64x32).
// Requires: M,N multiples of 128; K multiple of 16; lda multiple of 4.
// EPI: 0 = plain store, 1 = softplus(acc + bias[col])
// ---------------------------------------------------------------------------
template <int EPI>
__global__ void __launch_bounds__(256)
tgemm(const float* __restrict__ A, const float* __restrict__ Bm,
      float* __restrict__ C, int M, int N, int K,
      int lda, int ldb, int ldc, const float* __restrict__ bias)
{
    __shared__ float As[2][128][20];   // [m][k], stride 20 => conflict-free frags
    __shared__ float Bs[2][16][136];   // [k][n], stride 136 => conflict-free frags

    const int tid  = threadIdx.x;
    const int bm   = blockIdx.y * 128;
    const int bn   = blockIdx.x * 128;
    const int lane = tid & 31;
    const int wid  = tid >> 5;
    const int wm   = (wid & 1) * 64;     // warp row offset
    const int wn   = (wid >> 1) * 32;    // warp col offset
    const int g    = lane >> 2;          // group id (0..7)
    const int t    = lane & 3;           // thread-in-group (0..3)

    // global->smem load mapping
    const int ar  = tid >> 2;            // A row 0..63 (and +64)
    const int ac  = (tid & 3) * 4;       // A col chunk
    const int bk0 = tid >> 5;            // B k-row 0..7 (and +8)
    const int bc0 = (tid & 31) * 4;      // B col chunk

    const uint32_t sA = (uint32_t)__cvta_generic_to_shared(As);
    const uint32_t sB = (uint32_t)__cvta_generic_to_shared(Bs);
    const uint32_t sAbuf = 128 * 20 * 4;
    const uint32_t sBbuf = 16 * 136 * 4;
    const uint32_t sA0 = sA + (ar * 20 + ac) * 4;
    const uint32_t sA1 = sA + ((ar + 64) * 20 + ac) * 4;
    const uint32_t sB0 = sB + (bk0 * 136 + bc0) * 4;
    const uint32_t sB1 = sB + ((bk0 + 8) * 136 + bc0) * 4;

    const float* Ap0 = A + (size_t)(bm + ar) * lda + ac;
    const float* Ap1 = A + (size_t)(bm + ar + 64) * lda + ac;
    const float* Bp0 = Bm + (size_t)bk0 * ldb + bn + bc0;
    const float* Bp1 = Bm + (size_t)(bk0 + 8) * ldb + bn + bc0;

    float acc[4][4][4];
    #pragma unroll
    for (int mi = 0; mi < 4; mi++)
        #pragma unroll
        for (int ni = 0; ni < 4; ni++)
            #pragma unroll
            for (int r = 0; r < 4; r++) acc[mi][ni][r] = 0.0f;

    const int nIter = K / 16;

    // prologue: tile 0 -> buf 0
    {
        CPA16(sA0, Ap0);
        CPA16(sA1, Ap1);
        CPA16(sB0, Bp0);
        CPA16(sB1, Bp1);
        CPA_COMMIT();
    }

    int buf = 0;
    for (int it = 0; it < nIter; ++it) {
        if (it + 1 < nIter) {
            const int kk = (it + 1) * 16;
            const uint32_t off = (buf ^ 1) ? 1u : 0u;
            CPA16(sA0 + off * sAbuf, Ap0 + kk);
            CPA16(sA1 + off * sAbuf, Ap1 + kk);
            CPA16(sB0 + off * sBbuf, Bp0 + (size_t)kk * ldb);
            CPA16(sB1 + off * sBbuf, Bp1 + (size_t)kk * ldb);
            CPA_COMMIT();
            CPA_WAIT1();
        } else {
            CPA_WAIT0();
        }
        __syncthreads();

        #pragma unroll
        for (int s = 0; s < 2; s++) {
            uint32_t a[4][4], b[4][2];
            #pragma unroll
            for (int mi = 0; mi < 4; mi++) {
                const int m0 = wm + mi * 16;
                a[mi][0] = f2tf32(As[buf][m0 + g][s * 8 + t]);
                a[mi][1] = f2tf32(As[buf][m0 + g + 8][s * 8 + t]);
                a[mi][2] = f2tf32(As[buf][m0 + g][s * 8 + t + 4]);
                a[mi][3] = f2tf32(As[buf][m0 + g + 8][s * 8 + t + 4]);
            }
            #pragma unroll
            for (int ni = 0; ni < 4; ni++) {
                const int n0 = wn + ni * 8;
                b[ni][0] = f2tf32(Bs[buf][s * 8 + t][n0 + g]);
                b[ni][1] = f2tf32(Bs[buf][s * 8 + t + 4][n0 + g]);
            }
            #pragma unroll
            for (int mi = 0; mi < 4; mi++)
                #pragma unroll
                for (int ni = 0; ni < 4; ni++)
                    mma_tf32(acc[mi][ni], a[mi], b[ni]);
        }
        buf ^= 1;
        __syncthreads();
    }

    // epilogue
    #pragma unroll
    for (int mi = 0; mi < 4; mi++) {
        #pragma unroll
        for (int ni = 0; ni < 4; ni++) {
            const int row = bm + wm + mi * 16 + g;
            const int col = bn + wn + ni * 8 + 2 * t;
            float v0 = acc[mi][ni][0], v1 = acc[mi][ni][1];
            float v2 = acc[mi][ni][2], v3 = acc[mi][ni][3];
            if (EPI == 1) {
                const float b0 = bias[col], b1 = bias[col + 1];
                v0 = softplus_f(v0 + b0);
                v1 = softplus_f(v1 + b1);
                v2 = softplus_f(v2 + b0);
                v3 = softplus_f(v3 + b1);
            }
            *(float2*)(C + (size_t)row * ldc + col)       = make_float2(v0, v1);
            *(float2*)(C + (size_t)(row + 8) * ldc + col) = make_float2(v2, v3);
        }
    }
}

// ---------------------------------------------------------------------------
// Causal depthwise conv (k=4) + SiLU on the x half of xz
// ---------------------------------------------------------------------------
__global__ void conv_silu_kernel(const float* __restrict__ xz,
                                 const float* __restrict__ kw,   // (4, DI)
                                 const float* __restrict__ kb,   // (DI,)
                                 float* __restrict__ out)        // (NTOK, DI)
{
    int idx = blockIdx.x * blockDim.x + threadIdx.x;
    if (idx >= NTOK * DI) return;
    int d = idx & (DI - 1);
    int t = idx >> 11;           // token index b*L + l
    int l = t & (L_ - 1);

    float acc = kb[d];
    #pragma unroll
    for (int i = 0; i < DC; i++) {
        int ls = l - (DC - 1) + i;
        if (ls >= 0)
            acc = fmaf(xz[(size_t)(t - (DC - 1) + i) * (2 * DI) + d],
                       kw[i * DI + d], acc);
    }
    out[idx] = silu_f(acc);
}

// ---------------------------------------------------------------------------
// x_dbl = xconv @ Wx   (NTOK x 96, K=2048). 4 token rows per block to
// amortize Wx streaming through L2; 4 independent FMA chains.
// ---------------------------------------------------------------------------
#define XR 4
__global__ void __launch_bounds__(96)
xdbl_kernel(const float* __restrict__ xc, const float* __restrict__ Wx,
            float* __restrict__ out)
{
    __shared__ float sh[XR][DI];
    const int row0 = blockIdx.x * XR;
    const int col  = threadIdx.x;   // 0..95
    for (int i = col; i < XR * DI; i += 96)
        ((float*)sh)[i] = xc[(size_t)row0 * DI + i];
    __syncthreads();

    float acc[XR] = {0.0f, 0.0f, 0.0f, 0.0f};
    for (int k = 0; k < DI; k++) {
        float w = Wx[(size_t)k * XDBLW + col];
        #pragma unroll
        for (int r = 0; r < XR; r++)
            acc[r] = fmaf(sh[r][k], w, acc[r]);
    }
    #pragma unroll
    for (int r = 0; r < XR; r++)
        out[(size_t)(row0 + r) * XDBLW + col] = acc[r];
}

// ---------------------------------------------------------------------------
// Selective scan. One thread per (channel, state-n); 16-lane groups reduce y.
// Output: ybuf = (scan_y + u*Dskip) * silu(z)
// ---------------------------------------------------------------------------
__global__ void __launch_bounds__(256)
scan_kernel(const float* __restrict__ delta, const float* __restrict__ u,
            const float* __restrict__ xdbl,  const float* __restrict__ xz,
            const float* __restrict__ A_log, const float* __restrict__ Dskip,
            float* __restrict__ y)
{
    const int tid = threadIdx.x;
    const int grp = tid >> 4;                 // channel group within block
    const int n   = tid & 15;                 // state index
    const int c   = blockIdx.x * 16 + grp;    // global channel 0..B*DI-1
    const int b   = c >> 11;                  // / DI
    const int d   = c & (DI - 1);

    const float An = -__expf(A_log[d * NS + n]);
    const float Dd = Dskip[d];

    const float* drow = delta + (size_t)b * L_ * DI + d;
    const float* urow = u     + (size_t)b * L_ * DI + d;
    const float* zrow = xz    + (size_t)b * L_ * (2 * DI) + DI + d;
    const float* brow = xdbl  + (size_t)b * L_ * XDBLW + DTR + n;
    float*       yrow = y     + (size_t)b * L_ * DI + d;

    float x = 0.0f;
    for (int l = 0; l < L_; ++l) {
        float dv = drow[(size_t)l * DI];
        float uv = urow[(size_t)l * DI];
        float Bn = brow[(size_t)l * XDBLW];
        float Cn = brow[(size_t)l * XDBLW + NS];

        float dA = __expf(dv * An);
        x = fmaf(dA, x, dv * Bn * uv);

        float v = x * Cn;
        v += __shfl_xor_sync(0xffffffffu, v, 1, 16);
        v += __shfl_xor_sync(0xffffffffu, v, 2, 16);
        v += __shfl_xor_sync(0xffffffffu, v, 4, 16);
        v += __shfl_xor_sync(0xffffffffu, v, 8, 16);

        if (n == 0) {
            float zv = zrow[(size_t)l * (2 * DI)];
            yrow[(size_t)l * DI] = (v + uv * Dd) * silu_f(zv);
        }
    }
}

// ---------------------------------------------------------------------------
// Launch
// ---------------------------------------------------------------------------
extern "C" void kernel_launch(void* const* d_in, const int* in_sizes, int n_in,
                              void* d_out, int out_size)
{
    const float* hs      = (const float*)d_in[0];  // (B,L,DM)
    const float* Win     = (const float*)d_in[1];  // (DM, 2*DI)
    const float* Wx      = (const float*)d_in[2];  // (DI, 96)
    const float* Wdt     = (const float*)d_in[3];  // (DTR, DI)
    const float* dt_bias = (const float*)d_in[4];  // (DI,)
    const float* Wout    = (const float*)d_in[5];  // (DI, DM)
    const float* dwk     = (const float*)d_in[6];  // (4, DI)
    const float* dwb     = (const float*)d_in[7];  // (DI,)
    const float* A_log   = (const float*)d_in[8];  // (DI, NS)
    const float* Dskip   = (const float*)d_in[9];  // (DI,)
    float* out = (float*)d_out;

    float *xz, *xc, *xd, *dl, *yb;
    cudaGetSymbolAddress((void**)&xz, g_xz);
    cudaGetSymbolAddress((void**)&xc, g_xconv);
    cudaGetSymbolAddress((void**)&xd, g_xdbl);
    cudaGetSymbolAddress((void**)&dl, g_delta);
    cudaGetSymbolAddress((void**)&yb, g_ybuf);

    // 1) xz = hidden @ Win            (2048 x 4096, K=1024)   TF32 tensor cores
    tgemm<0><<<dim3(4096 / 128, 2048 / 128), 256>>>(
        hs, Win, xz, NTOK, 2 * DI, DM, DM, 2 * DI, 2 * DI, nullptr);

    // 2) depthwise causal conv + silu on x half
    conv_silu_kernel<<<(NTOK * DI + 255) / 256, 256>>>(xz, dwk, dwb, xc);

    // 3) x_dbl = xconv @ Wx           (2048 x 96, K=2048)     fp32 (small N)
    xdbl_kernel<<<NTOK / XR, 96>>>(xc, Wx, xd);

    // 4) delta = softplus(dt @ Wdt + dt_bias)   (2048 x 2048, K=64)  TF32
    tgemm<1><<<dim3(2048 / 128, 2048 / 128), 256>>>(
        xd, Wdt, dl, NTOK, DI, DTR, XDBLW, DI, DI, dt_bias);

    // 5) selective scan (+skip, *silu(z))
    scan_kernel<<<(B_ * DI) / 16, 256>>>(dl, xc, xd, xz, A_log, Dskip, yb);

    // 6) out = y @ Wout               (2048 x 1024, K=2048)   TF32
    tgemm<0><<<dim3(1024 / 128, 2048 / 128), 256>>>(
        yb, Wout, out, NTOK, DM, DI, DI, DM, DM, nullptr);
}